// round 3
// baseline (speedup 1.0000x reference)
#include <cuda_runtime.h>
#include <cstdint>
#include <cstddef>

#define NN 100000
#define EE 1600000
#define FIN 32
#define HH 16
#define CC 10

// ---------------- scratch (static __device__, no allocation) ----------------
__device__ __align__(16) float g_y[(size_t)NN * 32];     // per node: y0[0..15] | y1[16..31] (one 128B line)
__device__ __align__(16) float g_r1[(size_t)NN * HH];    // x@root1 + b1
__device__ __align__(16) float g_agg1[(size_t)NN * HH];
__device__ float g_deg[NN];
__device__ __align__(16) float g_z[(size_t)NN * 32];     // per node: z0[0..9] | pad | z1[12..21] | pad
__device__ float g_r2[(size_t)NN * CC];                  // h@root2 + b2
__device__ __align__(16) float g_agg2[(size_t)NN * 12];  // padded stride 12 for 16B-aligned vector red

// ---------------- vector reductions (sm_90+) ----------------
__device__ __forceinline__ void red_add_v4(float* addr, float a, float b, float c, float d) {
    asm volatile("red.global.add.v4.f32 [%0], {%1, %2, %3, %4};"
                 :: "l"(__cvta_generic_to_global(addr)), "f"(a), "f"(b), "f"(c), "f"(d)
                 : "memory");
}
__device__ __forceinline__ void red_add_v2(float* addr, float a, float b) {
    asm volatile("red.global.add.v2.f32 [%0], {%1, %2};"
                 :: "l"(__cvta_generic_to_global(addr)), "f"(a), "f"(b)
                 : "memory");
}

// ---------------- kernel 1: zero accumulators ----------------
__global__ void prep_kernel() {
    int i = blockIdx.x * blockDim.x + threadIdx.x;
    if (i < NN * HH) g_agg1[i] = 0.0f;     // 1.6M
    if (i < NN * 12) g_agg2[i] = 0.0f;     // 1.2M
    if (i < NN)      g_deg[i]  = 0.0f;
}

// ---------------- kernel 2: per-node transform layer 1 ----------------
// thread = (node_group, o); 4 nodes per thread; block = 256 threads -> 64 nodes
__global__ void transform1_kernel(const float* __restrict__ x,
                                  const float* __restrict__ W1,
                                  const float* __restrict__ root1,
                                  const float* __restrict__ b1) {
    __shared__ float sW0[FIN * HH], sW1[FIN * HH], sR[FIN * HH], sB[HH];
    __shared__ float sx[64 * FIN];
    int tid = threadIdx.x;
    for (int i = tid; i < FIN * HH; i += 256) {
        sW0[i] = W1[i];
        sW1[i] = W1[FIN * HH + i];
        sR[i]  = root1[i];
    }
    if (tid < HH) sB[tid] = b1[tid];

    int base = blockIdx.x * 64;
    int nvalid = min(64, NN - base);
    {
        const float4* xg = (const float4*)(x + (size_t)base * FIN);
        float4* sx4 = (float4*)sx;
        int tot4 = nvalid * (FIN / 4);
        for (int i = tid; i < tot4; i += 256) sx4[i] = xg[i];
    }
    __syncthreads();

    int o = tid & 15;
    int g = tid >> 4;
    float a0[4] = {0, 0, 0, 0};
    float a1[4] = {0, 0, 0, 0};
    float ar[4];
    float bv = sB[o];
#pragma unroll
    for (int j = 0; j < 4; j++) ar[j] = bv;

#pragma unroll
    for (int i = 0; i < FIN; i++) {
        float w0 = sW0[i * HH + o];
        float w1 = sW1[i * HH + o];
        float wr = sR[i * HH + o];
#pragma unroll
        for (int j = 0; j < 4; j++) {
            float xv = sx[(g * 4 + j) * FIN + i];
            a0[j] = fmaf(xv, w0, a0[j]);
            a1[j] = fmaf(xv, w1, a1[j]);
            ar[j] = fmaf(xv, wr, ar[j]);
        }
    }
#pragma unroll
    for (int j = 0; j < 4; j++) {
        int n = base + g * 4 + j;
        if (n < NN) {
            g_y[(size_t)n * 32 + o]      = a0[j];
            g_y[(size_t)n * 32 + 16 + o] = a1[j];
            g_r1[(size_t)n * HH + o]     = ar[j];
        }
    }
}

// ---------------- kernel 3: edge scatter layer 1 ----------------
__global__ void edge1_kernel(const int* __restrict__ edge_index,
                             const float* __restrict__ edge_attr) {
    int e = blockIdx.x * blockDim.x + threadIdx.x;
    if (e >= EE) return;
    float v  = edge_attr[e];                     // v = edge_attr * (K-1), K=2
    float w0 = fmaxf(0.0f, 1.0f - fabsf(v));
    float w1 = fmaxf(0.0f, 1.0f - fabsf(v - 1.0f));
    int s = edge_index[e];
    int d = edge_index[EE + e];
    if ((unsigned)s >= NN || (unsigned)d >= NN) return;

    const float4* y = (const float4*)(g_y + (size_t)s * 32);
    float4 p0 = y[0], p1 = y[1], p2 = y[2], p3 = y[3];   // y0
    float4 q0 = y[4], q1 = y[5], q2 = y[6], q3 = y[7];   // y1

    float* dst = g_agg1 + (size_t)d * HH;
    red_add_v4(dst + 0,  fmaf(w0, p0.x, w1 * q0.x), fmaf(w0, p0.y, w1 * q0.y),
                         fmaf(w0, p0.z, w1 * q0.z), fmaf(w0, p0.w, w1 * q0.w));
    red_add_v4(dst + 4,  fmaf(w0, p1.x, w1 * q1.x), fmaf(w0, p1.y, w1 * q1.y),
                         fmaf(w0, p1.z, w1 * q1.z), fmaf(w0, p1.w, w1 * q1.w));
    red_add_v4(dst + 8,  fmaf(w0, p2.x, w1 * q2.x), fmaf(w0, p2.y, w1 * q2.y),
                         fmaf(w0, p2.z, w1 * q2.z), fmaf(w0, p2.w, w1 * q2.w));
    red_add_v4(dst + 12, fmaf(w0, p3.x, w1 * q3.x), fmaf(w0, p3.y, w1 * q3.y),
                         fmaf(w0, p3.z, w1 * q3.z), fmaf(w0, p3.w, w1 * q3.w));
    atomicAdd(&g_deg[d], 1.0f);
}

// ---------------- kernel 4: finalize layer 1 (mean + root + elu) + transform layer 2 ----------------
__global__ void node1_kernel(const float* __restrict__ W2,
                             const float* __restrict__ root2,
                             const float* __restrict__ b2) {
    __shared__ float sW0[HH * CC], sW1[HH * CC], sR[HH * CC], sB[CC];
    int tid = threadIdx.x;
    for (int i = tid; i < HH * CC; i += blockDim.x) {
        sW0[i] = W2[i];
        sW1[i] = W2[HH * CC + i];
        sR[i]  = root2[i];
    }
    if (tid < CC) sB[tid] = b2[tid];
    __syncthreads();

    int n = blockIdx.x * blockDim.x + tid;
    if (n >= NN) return;

    float invd = 1.0f / fmaxf(g_deg[n], 1.0f);
    float h[HH];
    const float4* ag = (const float4*)(g_agg1 + (size_t)n * HH);
    const float4* rr = (const float4*)(g_r1 + (size_t)n * HH);
#pragma unroll
    for (int k = 0; k < 4; k++) {
        float4 a = ag[k];
        float4 r = rr[k];
        float t;
        t = fmaf(a.x, invd, r.x); h[k * 4 + 0] = (t > 0.0f) ? t : expm1f(t);
        t = fmaf(a.y, invd, r.y); h[k * 4 + 1] = (t > 0.0f) ? t : expm1f(t);
        t = fmaf(a.z, invd, r.z); h[k * 4 + 2] = (t > 0.0f) ? t : expm1f(t);
        t = fmaf(a.w, invd, r.w); h[k * 4 + 3] = (t > 0.0f) ? t : expm1f(t);
    }

#pragma unroll
    for (int o = 0; o < CC; o++) {
        float z0 = 0.0f, z1 = 0.0f, r = sB[o];
#pragma unroll
        for (int i = 0; i < HH; i++) {
            float hv = h[i];
            z0 = fmaf(hv, sW0[i * CC + o], z0);
            z1 = fmaf(hv, sW1[i * CC + o], z1);
            r  = fmaf(hv, sR[i * CC + o], r);
        }
        g_z[(size_t)n * 32 + o]      = z0;
        g_z[(size_t)n * 32 + 12 + o] = z1;
        g_r2[(size_t)n * CC + o]     = r;
    }
}

// ---------------- kernel 5: edge scatter layer 2 ----------------
__global__ void edge2_kernel(const int* __restrict__ edge_index,
                             const float* __restrict__ edge_attr) {
    int e = blockIdx.x * blockDim.x + threadIdx.x;
    if (e >= EE) return;
    float v  = edge_attr[e];
    float w0 = fmaxf(0.0f, 1.0f - fabsf(v));
    float w1 = fmaxf(0.0f, 1.0f - fabsf(v - 1.0f));
    int s = edge_index[e];
    int d = edge_index[EE + e];
    if ((unsigned)s >= NN || (unsigned)d >= NN) return;

    const float4* z = (const float4*)(g_z + (size_t)s * 32);
    float4 a0 = z[0], a1 = z[1], a2 = z[2];   // z0 in floats 0..9
    float4 b0 = z[3], b1 = z[4], b2 = z[5];   // z1 in floats 12..21

    float* dst = g_agg2 + (size_t)d * 12;
    red_add_v4(dst + 0, fmaf(w0, a0.x, w1 * b0.x), fmaf(w0, a0.y, w1 * b0.y),
                        fmaf(w0, a0.z, w1 * b0.z), fmaf(w0, a0.w, w1 * b0.w));
    red_add_v4(dst + 4, fmaf(w0, a1.x, w1 * b1.x), fmaf(w0, a1.y, w1 * b1.y),
                        fmaf(w0, a1.z, w1 * b1.z), fmaf(w0, a1.w, w1 * b1.w));
    red_add_v2(dst + 8, fmaf(w0, a2.x, w1 * b2.x), fmaf(w0, a2.y, w1 * b2.y));
}

// ---------------- kernel 6: finalize layer 2 + log_softmax ----------------
__global__ void out_kernel(float* __restrict__ out) {
    int n = blockIdx.x * blockDim.x + threadIdx.x;
    if (n >= NN) return;
    float invd = 1.0f / fmaxf(g_deg[n], 1.0f);
    float o[CC];
#pragma unroll
    for (int k = 0; k < CC; k++)
        o[k] = fmaf(g_agg2[(size_t)n * 12 + k], invd, g_r2[(size_t)n * CC + k]);
    float m = o[0];
#pragma unroll
    for (int k = 1; k < CC; k++) m = fmaxf(m, o[k]);
    float s = 0.0f;
#pragma unroll
    for (int k = 0; k < CC; k++) s += expf(o[k] - m);
    float l = m + logf(s);
#pragma unroll
    for (int k = 0; k < CC; k++) out[(size_t)n * CC + k] = o[k] - l;
}

// ---------------- launcher ----------------
extern "C" void kernel_launch(void* const* d_in, const int* in_sizes, int n_in,
                              void* d_out, int out_size) {
    const float* x     = (const float*)d_in[0];
    const int*   ei    = (const int*)d_in[1];     // int32 (JAX x64 disabled)
    const float* ea    = (const float*)d_in[2];
    const float* W1    = (const float*)d_in[3];
    const float* root1 = (const float*)d_in[4];
    const float* b1    = (const float*)d_in[5];
    const float* W2    = (const float*)d_in[6];
    const float* root2 = (const float*)d_in[7];
    const float* b2    = (const float*)d_in[8];
    float*       out   = (float*)d_out;

    const int TB = 256;
    int eBlocks = (EE + TB - 1) / TB;                 // 6250
    int zBlocks = (NN * HH + TB - 1) / TB;            // covers all zero-init ranges
    int nBlocks = (NN + TB - 1) / TB;                 // 391
    int tBlocks = (NN + 63) / 64;                     // 1563

    prep_kernel<<<zBlocks, TB>>>();
    transform1_kernel<<<tBlocks, TB>>>(x, W1, root1, b1);
    edge1_kernel<<<eBlocks, TB>>>(ei, ea);
    node1_kernel<<<nBlocks, TB>>>(W2, root2, b2);
    edge2_kernel<<<eBlocks, TB>>>(ei, ea);
    out_kernel<<<nBlocks, TB>>>(out);
}

// round 4
// speedup vs baseline: 1.6989x; 1.6989x over previous
#include <cuda_runtime.h>
#include <cuda_fp16.h>
#include <cstdint>
#include <cstddef>

#define NN 100000
#define EE 1600000
#define FIN 32
#define HH 16
#define CC 10

// ---------------- scratch (static __device__, no allocation) ----------------
__device__ __align__(16) float  g_meta[(size_t)EE * 4];   // per edge: {src, dst, w0, w1} (ints as float bits)
__device__ __align__(16) __half g_yh[(size_t)NN * 32];    // per node: 16x half2(y0[o],y1[o]) = 64B row
__device__ __align__(16) float  g_r1[(size_t)NN * HH];    // x@root1 + b1
__device__ __align__(16) float  g_agg1[(size_t)NN * HH];
__device__ int   g_degi[NN];
__device__ __align__(16) __half g_zh[(size_t)NN * 24];    // per node: 10x half2(z0,z1) + 2 pad pairs = 48B row
__device__ __align__(16) float  g_r2[(size_t)NN * 12];    // h@root2 + b2, padded stride 12
__device__ __align__(16) float  g_agg2[(size_t)NN * 12];  // padded stride 12

// ---------------- vector reductions (sm_90+) ----------------
__device__ __forceinline__ void red_add_v4(float* addr, float a, float b, float c, float d) {
    asm volatile("red.global.add.v4.f32 [%0], {%1, %2, %3, %4};"
                 :: "l"(__cvta_generic_to_global(addr)), "f"(a), "f"(b), "f"(c), "f"(d)
                 : "memory");
}

// ---------------- kernel 1: zero accumulators ----------------
__global__ void zero_kernel() {
    int i = blockIdx.x * blockDim.x + threadIdx.x;
    if (i < NN * HH) g_agg1[i] = 0.0f;     // 1.6M
    if (i < NN * 12) g_agg2[i] = 0.0f;     // 1.2M
    if (i < NN)      g_degi[i] = 0;
}

// ---------------- kernel 2: edge meta build + degree histogram ----------------
__global__ void meta_kernel(const int* __restrict__ edge_index,
                            const float* __restrict__ edge_attr) {
    int e = blockIdx.x * blockDim.x + threadIdx.x;
    if (e >= EE) return;
    int s = edge_index[e];
    int d = edge_index[EE + e];
    float v = edge_attr[e];                      // in [0,1); K=2 => basis = {1-v, v}
    float w0 = 1.0f - v;
    float w1 = v;
    if ((unsigned)s >= NN) { s = 0; w0 = w1 = 0.0f; }
    if ((unsigned)d >= NN) { d = 0; w0 = w1 = 0.0f; }
    else atomicAdd(&g_degi[d], 1);
    float4 m = make_float4(__int_as_float(s), __int_as_float(d), w0, w1);
    ((float4*)g_meta)[e] = m;
}

// ---------------- kernel 3: per-node transform layer 1 ----------------
// 4 nodes per thread-group; block = 256 threads -> 64 nodes/block
__global__ void transform1_kernel(const float* __restrict__ x,
                                  const float* __restrict__ W1,
                                  const float* __restrict__ root1,
                                  const float* __restrict__ b1) {
    __shared__ float sW0[FIN * HH], sW1[FIN * HH], sR[FIN * HH], sB[HH];
    __shared__ float sx[64 * FIN];
    int tid = threadIdx.x;
    for (int i = tid; i < FIN * HH; i += 256) {
        sW0[i] = W1[i];
        sW1[i] = W1[FIN * HH + i];
        sR[i]  = root1[i];
    }
    if (tid < HH) sB[tid] = b1[tid];

    int base = blockIdx.x * 64;
    int nvalid = min(64, NN - base);
    {
        const float4* xg = (const float4*)(x + (size_t)base * FIN);
        float4* sx4 = (float4*)sx;
        int tot4 = nvalid * (FIN / 4);
        for (int i = tid; i < tot4; i += 256) sx4[i] = xg[i];
    }
    __syncthreads();

    int o = tid & 15;
    int g = tid >> 4;
    float a0[4] = {0, 0, 0, 0};
    float a1[4] = {0, 0, 0, 0};
    float ar[4];
    float bv = sB[o];
#pragma unroll
    for (int j = 0; j < 4; j++) ar[j] = bv;

#pragma unroll
    for (int i = 0; i < FIN; i++) {
        float w0 = sW0[i * HH + o];
        float w1 = sW1[i * HH + o];
        float wr = sR[i * HH + o];
#pragma unroll
        for (int j = 0; j < 4; j++) {
            float xv = sx[(g * 4 + j) * FIN + i];
            a0[j] = fmaf(xv, w0, a0[j]);
            a1[j] = fmaf(xv, w1, a1[j]);
            ar[j] = fmaf(xv, wr, ar[j]);
        }
    }
#pragma unroll
    for (int j = 0; j < 4; j++) {
        int n = base + g * 4 + j;
        if (n < NN) {
            ((__half2*)g_yh)[(size_t)n * 16 + o] = __floats2half2_rn(a0[j], a1[j]);
            g_r1[(size_t)n * HH + o] = ar[j];
        }
    }
}

// ---------------- kernel 4: edge scatter layer 1 (4 lanes per edge) ----------------
__global__ void edge1_kernel() {
    int t = blockIdx.x * blockDim.x + threadIdx.x;
    int e = t >> 2;
    int q = t & 3;
    if (e >= EE) return;
    float4 m = ((const float4*)g_meta)[e];     // broadcast across the 4 lanes
    int s = __float_as_int(m.x);
    int d = __float_as_int(m.y);
    float w0 = m.z, w1 = m.w;

    float4 raw = ((const float4*)(g_yh + (size_t)s * 32))[q];   // 4 half2 pairs = features 4q..4q+3
    const __half2* hp = (const __half2*)&raw;
    float2 p0 = __half22float2(hp[0]);
    float2 p1 = __half22float2(hp[1]);
    float2 p2 = __half22float2(hp[2]);
    float2 p3 = __half22float2(hp[3]);

    red_add_v4(g_agg1 + (size_t)d * HH + q * 4,
               fmaf(w0, p0.x, w1 * p0.y), fmaf(w0, p1.x, w1 * p1.y),
               fmaf(w0, p2.x, w1 * p2.y), fmaf(w0, p3.x, w1 * p3.y));
}

// ---------------- kernel 5: finalize layer 1 (mean+root+elu) + transform layer 2 ----------------
__global__ void __launch_bounds__(256, 2) node1_kernel(const float* __restrict__ W2,
                                                       const float* __restrict__ root2,
                                                       const float* __restrict__ b2) {
    __shared__ float sW0[HH * CC], sW1[HH * CC], sR[HH * CC], sB[CC];
    int tid = threadIdx.x;
    for (int i = tid; i < HH * CC; i += 256) {
        sW0[i] = W2[i];
        sW1[i] = W2[HH * CC + i];
        sR[i]  = root2[i];
    }
    if (tid < CC) sB[tid] = b2[tid];
    __syncthreads();

    int n = blockIdx.x * 256 + tid;
    if (n >= NN) return;

    float invd = 1.0f / fmaxf((float)g_degi[n], 1.0f);
    float h[HH];
    const float4* ag = (const float4*)(g_agg1 + (size_t)n * HH);
    const float4* rr = (const float4*)(g_r1 + (size_t)n * HH);
#pragma unroll
    for (int k = 0; k < 4; k++) {
        float4 a = ag[k];
        float4 r = rr[k];
        float t;
        t = fmaf(a.x, invd, r.x); h[k * 4 + 0] = (t > 0.0f) ? t : (__expf(t) - 1.0f);
        t = fmaf(a.y, invd, r.y); h[k * 4 + 1] = (t > 0.0f) ? t : (__expf(t) - 1.0f);
        t = fmaf(a.z, invd, r.z); h[k * 4 + 2] = (t > 0.0f) ? t : (__expf(t) - 1.0f);
        t = fmaf(a.w, invd, r.w); h[k * 4 + 3] = (t > 0.0f) ? t : (__expf(t) - 1.0f);
    }

    __half2 zh[12];
    float   rv[12];
#pragma unroll 2
    for (int o = 0; o < CC; o++) {
        float z0 = 0.0f, z1 = 0.0f, r = sB[o];
#pragma unroll
        for (int i = 0; i < HH; i++) {
            float hv = h[i];
            z0 = fmaf(hv, sW0[i * CC + o], z0);
            z1 = fmaf(hv, sW1[i * CC + o], z1);
            r  = fmaf(hv, sR[i * CC + o], r);
        }
        zh[o] = __floats2half2_rn(z0, z1);
        rv[o] = r;
    }
    zh[10] = __floats2half2_rn(0.0f, 0.0f);
    zh[11] = zh[10];
    rv[10] = rv[11] = 0.0f;

    float4* zp = (float4*)(g_zh + (size_t)n * 24);
    const float4* zsrc = (const float4*)zh;
    zp[0] = zsrc[0]; zp[1] = zsrc[1]; zp[2] = zsrc[2];
    float4* rp = (float4*)(g_r2 + (size_t)n * 12);
    const float4* rsrc = (const float4*)rv;
    rp[0] = rsrc[0]; rp[1] = rsrc[1]; rp[2] = rsrc[2];
}

// ---------------- kernel 6: edge scatter layer 2 (4 lanes per edge, 3 active) ----------------
__global__ void edge2_kernel() {
    int t = blockIdx.x * blockDim.x + threadIdx.x;
    int e = t >> 2;
    int q = t & 3;
    if (e >= EE) return;
    float4 m = ((const float4*)g_meta)[e];
    if (q >= 3) return;
    int s = __float_as_int(m.x);
    int d = __float_as_int(m.y);
    float w0 = m.z, w1 = m.w;

    float4 raw = ((const float4*)(g_zh + (size_t)s * 24))[q];   // pairs 4q..4q+3 (pads are zero)
    const __half2* hp = (const __half2*)&raw;
    float2 p0 = __half22float2(hp[0]);
    float2 p1 = __half22float2(hp[1]);
    float2 p2 = __half22float2(hp[2]);
    float2 p3 = __half22float2(hp[3]);

    red_add_v4(g_agg2 + (size_t)d * 12 + q * 4,
               fmaf(w0, p0.x, w1 * p0.y), fmaf(w0, p1.x, w1 * p1.y),
               fmaf(w0, p2.x, w1 * p2.y), fmaf(w0, p3.x, w1 * p3.y));
}

// ---------------- kernel 7: finalize layer 2 + log_softmax ----------------
__global__ void out_kernel(float* __restrict__ out) {
    int n = blockIdx.x * blockDim.x + threadIdx.x;
    if (n >= NN) return;
    float invd = 1.0f / fmaxf((float)g_degi[n], 1.0f);
    float o[12];
    const float4* ap = (const float4*)(g_agg2 + (size_t)n * 12);
    const float4* rp = (const float4*)(g_r2 + (size_t)n * 12);
#pragma unroll
    for (int k = 0; k < 3; k++) {
        float4 a = ap[k];
        float4 r = rp[k];
        o[k * 4 + 0] = fmaf(a.x, invd, r.x);
        o[k * 4 + 1] = fmaf(a.y, invd, r.y);
        o[k * 4 + 2] = fmaf(a.z, invd, r.z);
        o[k * 4 + 3] = fmaf(a.w, invd, r.w);
    }
    float mx = o[0];
#pragma unroll
    for (int k = 1; k < CC; k++) mx = fmaxf(mx, o[k]);
    float s = 0.0f;
#pragma unroll
    for (int k = 0; k < CC; k++) s += __expf(o[k] - mx);
    float l = mx + __logf(s);
    float2* op = (float2*)(out + (size_t)n * CC);
#pragma unroll
    for (int k = 0; k < 5; k++)
        op[k] = make_float2(o[2 * k] - l, o[2 * k + 1] - l);
}

// ---------------- launcher ----------------
extern "C" void kernel_launch(void* const* d_in, const int* in_sizes, int n_in,
                              void* d_out, int out_size) {
    const float* x     = (const float*)d_in[0];
    const int*   ei    = (const int*)d_in[1];     // int32 (JAX x64 disabled)
    const float* ea    = (const float*)d_in[2];
    const float* W1    = (const float*)d_in[3];
    const float* root1 = (const float*)d_in[4];
    const float* b1    = (const float*)d_in[5];
    const float* W2    = (const float*)d_in[6];
    const float* root2 = (const float*)d_in[7];
    const float* b2    = (const float*)d_in[8];
    float*       out   = (float*)d_out;

    const int TB = 256;
    int zBlocks  = (NN * HH + TB - 1) / TB;           // 6250 — covers all zero ranges
    int mBlocks  = (EE + TB - 1) / TB;                // 6250
    int tBlocks  = (NN + 63) / 64;                    // 1563
    int e4Blocks = (EE * 4 + TB - 1) / TB;            // 25000
    int nBlocks  = (NN + TB - 1) / TB;                // 391

    zero_kernel<<<zBlocks, TB>>>();
    meta_kernel<<<mBlocks, TB>>>(ei, ea);
    transform1_kernel<<<tBlocks, TB>>>(x, W1, root1, b1);
    edge1_kernel<<<e4Blocks, TB>>>();
    node1_kernel<<<nBlocks, TB>>>(W2, root2, b2);
    edge2_kernel<<<e4Blocks, TB>>>();
    out_kernel<<<nBlocks, TB>>>(out);
}